// round 14
// baseline (speedup 1.0000x reference)
#include <cuda_runtime.h>
#include <cuda_bf16.h>
#include <cuda_fp16.h>
#include <cstdint>

// ---------------------------------------------------------------------------
// InfoNCE loss, GB300 sm_103a.  B=64, C=256, H=W=16, NEG=16, K-steps=5, SKIP=1
// R5: score gather traffic halved — negatives read an fp16 copy of ztwk
// (written in the GEMM epilogue); main dot stays fp32.
// ---------------------------------------------------------------------------

#define NNEG 16

__device__ __constant__ int d_rowbase[6] = {0, 14336, 27648, 39936, 51200, 61440};

// Scratch (static device globals; no allocation allowed)
__device__ __align__(16) __nv_bfloat16 g_zt_hi[16384 * 256];
__device__ __align__(16) __nv_bfloat16 g_zt_lo[16384 * 256];
__device__ __align__(16) float         g_ct[16384 * 256];
__device__ __align__(16) __nv_bfloat16 g_w_hi[5 * 256 * 256];
__device__ __align__(16) __nv_bfloat16 g_w_lo[5 * 256 * 256];
__device__ __align__(16) float         g_ztwk[61440 * 256];
__device__ __align__(16) __half        g_ztwk_h[61440 * 256];
__device__ float                       g_loss[61440];

__device__ __forceinline__ uint32_t smem_u32(const void* p) {
    uint32_t a;
    asm("{ .reg .u64 t; cvta.to.shared.u64 t, %1; cvt.u32.u64 %0, t; }"
        : "=r"(a) : "l"(p));
    return a;
}
__device__ __forceinline__ uint32_t sw128(uint32_t off) {
    return off ^ ((off >> 3) & 0x70);
}
__device__ __forceinline__ void ldmatrix_x4(uint32_t* r, uint32_t addr) {
    asm volatile("ldmatrix.sync.aligned.m8n8.x4.shared.b16 {%0,%1,%2,%3}, [%4];"
                 : "=r"(r[0]), "=r"(r[1]), "=r"(r[2]), "=r"(r[3]) : "r"(addr));
}
__device__ __forceinline__ void mma_bf16(float* d, const uint32_t* a,
                                         uint32_t b0, uint32_t b1) {
    asm volatile(
        "mma.sync.aligned.m16n8k16.row.col.f32.bf16.bf16.f32 "
        "{%0,%1,%2,%3}, {%4,%5,%6,%7}, {%8,%9}, {%0,%1,%2,%3};"
        : "+f"(d[0]), "+f"(d[1]), "+f"(d[2]), "+f"(d[3])
        : "r"(a[0]), "r"(a[1]), "r"(a[2]), "r"(a[3]), "r"(b0), "r"(b1));
}

// ---------------------------------------------------------------------------
// 1) split/transpose: blocks 0..1023 -> z (bf16 hi/lo, transposed)
//    blocks 1024..2047 -> c (fp32, transposed), blocks 2048..3327 -> W split
// ---------------------------------------------------------------------------
__global__ void split_kernel(const float* __restrict__ z,
                             const float* __restrict__ c,
                             const float* __restrict__ Wk) {
    int bid = blockIdx.x;
    int tid = threadIdx.x;

    if (bid >= 2048) {
        int e = (bid - 2048) * 256 + tid;  // < 327680
        float v = Wk[e];
        __nv_bfloat16 hi = __float2bfloat16(v);
        g_w_hi[e] = hi;
        g_w_lo[e] = __float2bfloat16(v - __bfloat162float(hi));
        return;
    }

    bool is_z = (bid < 1024);
    const float* src = is_z ? z : c;
    int local = bid & 1023;
    int b = local >> 4;
    int h = local & 15;
    int i = tid;  // channel 0..255

    const float4* p = (const float4*)(src + (size_t)b * 65536 + (size_t)i * 256 + h * 16);
    float vals[16];
    ((float4*)vals)[0] = p[0];
    ((float4*)vals)[1] = p[1];
    ((float4*)vals)[2] = p[2];
    ((float4*)vals)[3] = p[3];

    if (is_z) {
#pragma unroll
        for (int w = 0; w < 16; w++) {
            size_t idx = (size_t)((h * 16 + w) * 64 + b) * 256 + i;
            float v = vals[w];
            __nv_bfloat16 hi = __float2bfloat16(v);
            g_zt_hi[idx] = hi;
            g_zt_lo[idx] = __float2bfloat16(v - __bfloat162float(hi));
        }
    } else {
#pragma unroll
        for (int w = 0; w < 16; w++) {
            g_ct[(size_t)((h * 16 + w) * 64 + b) * 256 + i] = vals[w];
        }
    }
}

// ---------------------------------------------------------------------------
// 2) bf16 mma.sync GEMM: 960 CTAs; CTA tile 128(M) x 128(N), K=256 in 4
//    chunks of 64. 8 warps arranged 4(M) x 2(N); warp tile 32x64.
//    D = Ahi*Whi + Ahi*Wlo + Alo*Whi (fp32 accum). Writes fp32 + fp16 copies.
// ---------------------------------------------------------------------------
#define SMT_A 16384                       // bytes per tile (128 x 64 bf16)
#define SM_AHI 0
#define SM_ALO (SMT_A)
#define SM_WHI (SMT_A * 2)
#define SM_WLO (SMT_A * 3)
#define SM_TOTAL (SMT_A * 4)              // 64 KB

__global__ void __launch_bounds__(256) gemm_mma_kernel() {
    extern __shared__ char smem[];
    uint32_t sb = smem_u32(smem);
    int tid = threadIdx.x;
    int wid = tid >> 5;
    int lane = tid & 31;
    int wm = wid & 3;        // 0..3 -> M offset wm*32
    int wn = wid >> 2;       // 0..1 -> N offset wn*64

    int bid = blockIdx.x;
    int mtile = bid >> 1;    // 0..479
    int nt = bid & 1;        // 0..1

    int kidx = 0;
#pragma unroll
    for (int k = 1; k < 5; k++)
        if (mtile * 128 >= d_rowbase[k]) kidx = k;
    int r0 = mtile * 128 - d_rowbase[kidx];
    int zrow0 = (kidx + 2) * 1024 + r0;

    const __nv_bfloat16* Ahi = g_zt_hi + (size_t)zrow0 * 256;
    const __nv_bfloat16* Alo = g_zt_lo + (size_t)zrow0 * 256;
    const __nv_bfloat16* Whi = g_w_hi + (size_t)kidx * 65536 + (size_t)nt * 128 * 256;
    const __nv_bfloat16* Wlo = g_w_lo + (size_t)kidx * 65536 + (size_t)nt * 128 * 256;
    float* O = g_ztwk + (size_t)mtile * 128 * 256 + nt * 128;
    __half* Oh = g_ztwk_h + (size_t)mtile * 128 * 256 + nt * 128;

    float acc[2][8][4];
#pragma unroll
    for (int i = 0; i < 2; i++)
#pragma unroll
        for (int j = 0; j < 8; j++)
#pragma unroll
            for (int q = 0; q < 4; q++) acc[i][j][q] = 0.0f;

    int lrow = lane & 15;
    int lhalf = (lane >> 4) * 16;

    for (int ch = 0; ch < 4; ch++) {
        // -------- stage smem: 4 tiles of 128 rows x 64 bf16, SW128 layout ----
#pragma unroll
        for (int u = 0; u < 4; u++) {
            int f = tid + u * 256;        // 0..1023 over 128 rows x 8 segs
            int row = f >> 3, seg = f & 7;
            size_t goff = (size_t)row * 256 + ch * 64 + seg * 8;
            uint32_t so = sw128(row * 128 + seg * 16);
            *(uint4*)(smem + SM_AHI + so) = *(const uint4*)(Ahi + goff);
            *(uint4*)(smem + SM_ALO + so) = *(const uint4*)(Alo + goff);
            *(uint4*)(smem + SM_WHI + so) = *(const uint4*)(Whi + goff);
            *(uint4*)(smem + SM_WLO + so) = *(const uint4*)(Wlo + goff);
        }
        __syncthreads();

        // -------- compute: 4 k16 steps --------------------------------------
#pragma unroll
        for (int ks = 0; ks < 4; ks++) {
            uint32_t a_hi[2][4], a_lo[2][4];
#pragma unroll
            for (int mr = 0; mr < 2; mr++) {
                uint32_t boff = (wm * 32 + mr * 16 + lrow) * 128 + ks * 32 + lhalf;
                uint32_t so = sw128(boff);
                ldmatrix_x4(a_hi[mr], sb + SM_AHI + so);
                ldmatrix_x4(a_lo[mr], sb + SM_ALO + so);
            }
            uint32_t b_hi[4][4], b_lo[4][4];
#pragma unroll
            for (int ng = 0; ng < 4; ng++) {
                uint32_t boff = (wn * 64 + ng * 16 + lrow) * 128 + ks * 32 + lhalf;
                uint32_t so = sw128(boff);
                ldmatrix_x4(b_hi[ng], sb + SM_WHI + so);
                ldmatrix_x4(b_lo[ng], sb + SM_WLO + so);
            }
#pragma unroll
            for (int mr = 0; mr < 2; mr++) {
#pragma unroll
                for (int ng = 0; ng < 4; ng++) {
                    mma_bf16(acc[mr][ng * 2],     a_hi[mr], b_hi[ng][0], b_hi[ng][2]);
                    mma_bf16(acc[mr][ng * 2],     a_hi[mr], b_lo[ng][0], b_lo[ng][2]);
                    mma_bf16(acc[mr][ng * 2],     a_lo[mr], b_hi[ng][0], b_hi[ng][2]);
                    mma_bf16(acc[mr][ng * 2 + 1], a_hi[mr], b_hi[ng][1], b_hi[ng][3]);
                    mma_bf16(acc[mr][ng * 2 + 1], a_hi[mr], b_lo[ng][1], b_lo[ng][3]);
                    mma_bf16(acc[mr][ng * 2 + 1], a_lo[mr], b_hi[ng][1], b_hi[ng][3]);
                }
            }
        }
        __syncthreads();
    }

    // -------- epilogue: write fp32 result + fp16 copy ------------------------
    int qrow = lane >> 2;
    int qcol = (lane & 3) * 2;
#pragma unroll
    for (int mr = 0; mr < 2; mr++) {
#pragma unroll
        for (int ntile = 0; ntile < 8; ntile++) {
            int col = wn * 64 + ntile * 8 + qcol;
            size_t r0o = (size_t)(wm * 32 + mr * 16 + qrow) * 256 + col;
            size_t r1o = r0o + 8 * 256;
            *(float2*)(O + r0o) = make_float2(acc[mr][ntile][0], acc[mr][ntile][1]);
            *(float2*)(O + r1o) = make_float2(acc[mr][ntile][2], acc[mr][ntile][3]);
            *(__half2*)(Oh + r0o) = __floats2half2_rn(acc[mr][ntile][0], acc[mr][ntile][1]);
            *(__half2*)(Oh + r1o) = __floats2half2_rn(acc[mr][ntile][2], acc[mr][ntile][3]);
        }
    }
}

// ---------------------------------------------------------------------------
// 3) score: one warp per row. Main dot in fp32, 16 gathered negatives in fp16.
// ---------------------------------------------------------------------------
__global__ void score_kernel(const int* __restrict__ i1, const int* __restrict__ i2,
                             const int* __restrict__ i3, const int* __restrict__ i4,
                             const int* __restrict__ i5) {
    int warp = (blockIdx.x * blockDim.x + threadIdx.x) >> 5;
    int lane = threadIdx.x & 31;
    if (warp >= 61440) return;
    int R = warp;

    int kidx = 0;
#pragma unroll
    for (int k = 1; k < 5; k++)
        if (R >= d_rowbase[k]) kidx = k;
    int base = d_rowbase[kidx];
    int r = R - base;

    const int* idx;
    switch (kidx) {
        case 0: idx = i1; break;
        case 1: idx = i2; break;
        case 2: idx = i3; break;
        case 3: idx = i4; break;
        default: idx = i5; break;
    }

    int c0 = lane * 8;
    const float* ctx = g_ct + (size_t)r * 256 + c0;
    float4 cxa = *(const float4*)ctx;
    float4 cxb = *(const float4*)(ctx + 4);

    float l[17];
    // main dot in fp32
    {
        const float* tr = g_ztwk + (size_t)R * 256 + c0;
        float4 ta = *(const float4*)tr;
        float4 tb = *(const float4*)(tr + 4);
        l[0] = cxa.x * ta.x + cxa.y * ta.y + cxa.z * ta.z + cxa.w * ta.w +
               cxb.x * tb.x + cxb.y * tb.y + cxb.z * tb.z + cxb.w * tb.w;
    }
    // 16 negatives from fp16 copy
#pragma unroll
    for (int t = 1; t < 17; t++) {
        int row = base + idx[r * NNEG + (t - 1)];
        const __half* tr = g_ztwk_h + (size_t)row * 256 + c0;
        uint4 u = *(const uint4*)tr;     // 8 halves
        float2 f0 = __half22float2(*(const __half2*)&u.x);
        float2 f1 = __half22float2(*(const __half2*)&u.y);
        float2 f2 = __half22float2(*(const __half2*)&u.z);
        float2 f3 = __half22float2(*(const __half2*)&u.w);
        l[t] = cxa.x * f0.x + cxa.y * f0.y + cxa.z * f1.x + cxa.w * f1.y +
               cxb.x * f2.x + cxb.y * f2.y + cxb.z * f3.x + cxb.w * f3.y;
    }

#pragma unroll
    for (int o = 16; o >= 1; o >>= 1) {
#pragma unroll
        for (int t = 0; t < 17; t++) l[t] += __shfl_xor_sync(0xffffffffu, l[t], o);
    }

    if (lane == 0) {
        float m = l[0];
#pragma unroll
        for (int t = 1; t < 17; t++) m = fmaxf(m, l[t]);
        float S = 0.0f;
#pragma unroll
        for (int t = 0; t < 17; t++) S += __expf(l[t] - m);
        float p0 = __expf(l[0] - m) / S;
        g_loss[R] = -__logf(p0 + 1e-11f);
    }
}

// ---------------------------------------------------------------------------
// 4) patchwise loss + count
// ---------------------------------------------------------------------------
__global__ void patch_kernel(float* __restrict__ out) {
    int p = blockIdx.x * blockDim.x + threadIdx.x;  // b*256+h*16+w
    if (p >= 16384) return;
    int b = p >> 8;
    int h = (p >> 4) & 15;
    int w = p & 15;

    float s = 0.0f;
#pragma unroll
    for (int k = 0; k < 5; k++) {
        int off = k + 2;
        int Hk = 14 - k;
        int base = d_rowbase[k];
        if (h >= off) s += g_loss[base + (h - off) * 1024 + w * 64 + b];
        if (h < Hk)   s += g_loss[base + h * 1024 + w * 64 + b];
    }
    out[1 + p] = s;

    if (b == 0) {
        float cnt = 0.0f;
#pragma unroll
        for (int k = 0; k < 5; k++) {
            int off = k + 2;
            int Hk = 14 - k;
            cnt += (h >= off ? 1.0f : 0.0f) + (h < Hk ? 1.0f : 0.0f);
        }
        out[16385 + h * 16 + w] = cnt;
    }
}

// ---------------------------------------------------------------------------
// 5) total loss
// ---------------------------------------------------------------------------
__global__ void total_kernel(float* __restrict__ out) {
    __shared__ float red[256];
    const float scale[5] = {1.0f / (14336.0f * 5.0f), 1.0f / (13312.0f * 5.0f),
                            1.0f / (12288.0f * 5.0f), 1.0f / (11264.0f * 5.0f),
                            1.0f / (10240.0f * 5.0f)};
    int tid = threadIdx.x;
    float s = 0.0f;
    for (int R = tid; R < 61440; R += 256) {
        int kidx = 0;
#pragma unroll
        for (int k = 1; k < 5; k++)
            if (R >= d_rowbase[k]) kidx = k;
        s += g_loss[R] * scale[kidx];
    }
    red[tid] = s;
    __syncthreads();
    for (int o = 128; o > 0; o >>= 1) {
        if (tid < o) red[tid] += red[tid + o];
        __syncthreads();
    }
    if (tid == 0) out[0] = red[0];
}

// ---------------------------------------------------------------------------
extern "C" void kernel_launch(void* const* d_in, const int* in_sizes, int n_in,
                              void* d_out, int out_size) {
    const float* z  = (const float*)d_in[0];
    const float* c  = (const float*)d_in[1];
    const float* Wk = (const float*)d_in[2];
    const int* i1 = (const int*)d_in[3];
    const int* i2 = (const int*)d_in[4];
    const int* i3 = (const int*)d_in[5];
    const int* i4 = (const int*)d_in[6];
    const int* i5 = (const int*)d_in[7];
    float* out = (float*)d_out;

    cudaFuncSetAttribute(gemm_mma_kernel,
                         cudaFuncAttributeMaxDynamicSharedMemorySize, SM_TOTAL);

    split_kernel<<<3328, 256>>>(z, c, Wk);
    gemm_mma_kernel<<<960, 256, SM_TOTAL>>>();
    score_kernel<<<7680, 256>>>(i1, i2, i3, i4, i5);
    patch_kernel<<<64, 256>>>(out);
    total_kernel<<<1, 256>>>(out);
}

// round 15
// speedup vs baseline: 1.0036x; 1.0036x over previous
#include <cuda_runtime.h>
#include <cuda_bf16.h>
#include <cuda_fp16.h>
#include <cstdint>

// ---------------------------------------------------------------------------
// InfoNCE loss, GB300 sm_103a.  B=64, C=256, H=W=16, NEG=16, K-steps=5, SKIP=1
// R5: score gather traffic halved — negatives read an fp16 copy of ztwk
// (written in the GEMM epilogue); main dot stays fp32.
// ---------------------------------------------------------------------------

#define NNEG 16

__device__ __constant__ int d_rowbase[6] = {0, 14336, 27648, 39936, 51200, 61440};

// Scratch (static device globals; no allocation allowed)
__device__ __align__(16) __nv_bfloat16 g_zt_hi[16384 * 256];
__device__ __align__(16) __nv_bfloat16 g_zt_lo[16384 * 256];
__device__ __align__(16) float         g_ct[16384 * 256];
__device__ __align__(16) __nv_bfloat16 g_w_hi[5 * 256 * 256];
__device__ __align__(16) __nv_bfloat16 g_w_lo[5 * 256 * 256];
__device__ __align__(16) float         g_ztwk[61440 * 256];
__device__ __align__(16) __half        g_ztwk_h[61440 * 256];
__device__ float                       g_loss[61440];

__device__ __forceinline__ uint32_t smem_u32(const void* p) {
    uint32_t a;
    asm("{ .reg .u64 t; cvta.to.shared.u64 t, %1; cvt.u32.u64 %0, t; }"
        : "=r"(a) : "l"(p));
    return a;
}
__device__ __forceinline__ uint32_t sw128(uint32_t off) {
    return off ^ ((off >> 3) & 0x70);
}
__device__ __forceinline__ void ldmatrix_x4(uint32_t* r, uint32_t addr) {
    asm volatile("ldmatrix.sync.aligned.m8n8.x4.shared.b16 {%0,%1,%2,%3}, [%4];"
                 : "=r"(r[0]), "=r"(r[1]), "=r"(r[2]), "=r"(r[3]) : "r"(addr));
}
__device__ __forceinline__ void mma_bf16(float* d, const uint32_t* a,
                                         uint32_t b0, uint32_t b1) {
    asm volatile(
        "mma.sync.aligned.m16n8k16.row.col.f32.bf16.bf16.f32 "
        "{%0,%1,%2,%3}, {%4,%5,%6,%7}, {%8,%9}, {%0,%1,%2,%3};"
        : "+f"(d[0]), "+f"(d[1]), "+f"(d[2]), "+f"(d[3])
        : "r"(a[0]), "r"(a[1]), "r"(a[2]), "r"(a[3]), "r"(b0), "r"(b1));
}

// ---------------------------------------------------------------------------
// 1) split/transpose: blocks 0..1023 -> z (bf16 hi/lo, transposed)
//    blocks 1024..2047 -> c (fp32, transposed), blocks 2048..3327 -> W split
// ---------------------------------------------------------------------------
__global__ void split_kernel(const float* __restrict__ z,
                             const float* __restrict__ c,
                             const float* __restrict__ Wk) {
    int bid = blockIdx.x;
    int tid = threadIdx.x;

    if (bid >= 2048) {
        int e = (bid - 2048) * 256 + tid;  // < 327680
        float v = Wk[e];
        __nv_bfloat16 hi = __float2bfloat16(v);
        g_w_hi[e] = hi;
        g_w_lo[e] = __float2bfloat16(v - __bfloat162float(hi));
        return;
    }

    bool is_z = (bid < 1024);
    const float* src = is_z ? z : c;
    int local = bid & 1023;
    int b = local >> 4;
    int h = local & 15;
    int i = tid;  // channel 0..255

    const float4* p = (const float4*)(src + (size_t)b * 65536 + (size_t)i * 256 + h * 16);
    float vals[16];
    ((float4*)vals)[0] = p[0];
    ((float4*)vals)[1] = p[1];
    ((float4*)vals)[2] = p[2];
    ((float4*)vals)[3] = p[3];

    if (is_z) {
#pragma unroll
        for (int w = 0; w < 16; w++) {
            size_t idx = (size_t)((h * 16 + w) * 64 + b) * 256 + i;
            float v = vals[w];
            __nv_bfloat16 hi = __float2bfloat16(v);
            g_zt_hi[idx] = hi;
            g_zt_lo[idx] = __float2bfloat16(v - __bfloat162float(hi));
        }
    } else {
#pragma unroll
        for (int w = 0; w < 16; w++) {
            g_ct[(size_t)((h * 16 + w) * 64 + b) * 256 + i] = vals[w];
        }
    }
}

// ---------------------------------------------------------------------------
// 2) bf16 mma.sync GEMM: 960 CTAs; CTA tile 128(M) x 128(N), K=256 in 4
//    chunks of 64. 8 warps arranged 4(M) x 2(N); warp tile 32x64.
//    D = Ahi*Whi + Ahi*Wlo + Alo*Whi (fp32 accum). Writes fp32 + fp16 copies.
// ---------------------------------------------------------------------------
#define SMT_A 16384                       // bytes per tile (128 x 64 bf16)
#define SM_AHI 0
#define SM_ALO (SMT_A)
#define SM_WHI (SMT_A * 2)
#define SM_WLO (SMT_A * 3)
#define SM_TOTAL (SMT_A * 4)              // 64 KB

__global__ void __launch_bounds__(256) gemm_mma_kernel() {
    extern __shared__ char smem[];
    uint32_t sb = smem_u32(smem);
    int tid = threadIdx.x;
    int wid = tid >> 5;
    int lane = tid & 31;
    int wm = wid & 3;        // 0..3 -> M offset wm*32
    int wn = wid >> 2;       // 0..1 -> N offset wn*64

    int bid = blockIdx.x;
    int mtile = bid >> 1;    // 0..479
    int nt = bid & 1;        // 0..1

    int kidx = 0;
#pragma unroll
    for (int k = 1; k < 5; k++)
        if (mtile * 128 >= d_rowbase[k]) kidx = k;
    int r0 = mtile * 128 - d_rowbase[kidx];
    int zrow0 = (kidx + 2) * 1024 + r0;

    const __nv_bfloat16* Ahi = g_zt_hi + (size_t)zrow0 * 256;
    const __nv_bfloat16* Alo = g_zt_lo + (size_t)zrow0 * 256;
    const __nv_bfloat16* Whi = g_w_hi + (size_t)kidx * 65536 + (size_t)nt * 128 * 256;
    const __nv_bfloat16* Wlo = g_w_lo + (size_t)kidx * 65536 + (size_t)nt * 128 * 256;
    float* O = g_ztwk + (size_t)mtile * 128 * 256 + nt * 128;
    __half* Oh = g_ztwk_h + (size_t)mtile * 128 * 256 + nt * 128;

    float acc[2][8][4];
#pragma unroll
    for (int i = 0; i < 2; i++)
#pragma unroll
        for (int j = 0; j < 8; j++)
#pragma unroll
            for (int q = 0; q < 4; q++) acc[i][j][q] = 0.0f;

    int lrow = lane & 15;
    int lhalf = (lane >> 4) * 16;

    for (int ch = 0; ch < 4; ch++) {
        // -------- stage smem: 4 tiles of 128 rows x 64 bf16, SW128 layout ----
#pragma unroll
        for (int u = 0; u < 4; u++) {
            int f = tid + u * 256;        // 0..1023 over 128 rows x 8 segs
            int row = f >> 3, seg = f & 7;
            size_t goff = (size_t)row * 256 + ch * 64 + seg * 8;
            uint32_t so = sw128(row * 128 + seg * 16);
            *(uint4*)(smem + SM_AHI + so) = *(const uint4*)(Ahi + goff);
            *(uint4*)(smem + SM_ALO + so) = *(const uint4*)(Alo + goff);
            *(uint4*)(smem + SM_WHI + so) = *(const uint4*)(Whi + goff);
            *(uint4*)(smem + SM_WLO + so) = *(const uint4*)(Wlo + goff);
        }
        __syncthreads();

        // -------- compute: 4 k16 steps --------------------------------------
#pragma unroll
        for (int ks = 0; ks < 4; ks++) {
            uint32_t a_hi[2][4], a_lo[2][4];
#pragma unroll
            for (int mr = 0; mr < 2; mr++) {
                uint32_t boff = (wm * 32 + mr * 16 + lrow) * 128 + ks * 32 + lhalf;
                uint32_t so = sw128(boff);
                ldmatrix_x4(a_hi[mr], sb + SM_AHI + so);
                ldmatrix_x4(a_lo[mr], sb + SM_ALO + so);
            }
            uint32_t b_hi[4][4], b_lo[4][4];
#pragma unroll
            for (int ng = 0; ng < 4; ng++) {
                uint32_t boff = (wn * 64 + ng * 16 + lrow) * 128 + ks * 32 + lhalf;
                uint32_t so = sw128(boff);
                ldmatrix_x4(b_hi[ng], sb + SM_WHI + so);
                ldmatrix_x4(b_lo[ng], sb + SM_WLO + so);
            }
#pragma unroll
            for (int mr = 0; mr < 2; mr++) {
#pragma unroll
                for (int ng = 0; ng < 4; ng++) {
                    mma_bf16(acc[mr][ng * 2],     a_hi[mr], b_hi[ng][0], b_hi[ng][2]);
                    mma_bf16(acc[mr][ng * 2],     a_hi[mr], b_lo[ng][0], b_lo[ng][2]);
                    mma_bf16(acc[mr][ng * 2],     a_lo[mr], b_hi[ng][0], b_hi[ng][2]);
                    mma_bf16(acc[mr][ng * 2 + 1], a_hi[mr], b_hi[ng][1], b_hi[ng][3]);
                    mma_bf16(acc[mr][ng * 2 + 1], a_hi[mr], b_lo[ng][1], b_lo[ng][3]);
                    mma_bf16(acc[mr][ng * 2 + 1], a_lo[mr], b_hi[ng][1], b_hi[ng][3]);
                }
            }
        }
        __syncthreads();
    }

    // -------- epilogue: write fp32 result + fp16 copy ------------------------
    int qrow = lane >> 2;
    int qcol = (lane & 3) * 2;
#pragma unroll
    for (int mr = 0; mr < 2; mr++) {
#pragma unroll
        for (int ntile = 0; ntile < 8; ntile++) {
            int col = wn * 64 + ntile * 8 + qcol;
            size_t r0o = (size_t)(wm * 32 + mr * 16 + qrow) * 256 + col;
            size_t r1o = r0o + 8 * 256;
            *(float2*)(O + r0o) = make_float2(acc[mr][ntile][0], acc[mr][ntile][1]);
            *(float2*)(O + r1o) = make_float2(acc[mr][ntile][2], acc[mr][ntile][3]);
            *(__half2*)(Oh + r0o) = __floats2half2_rn(acc[mr][ntile][0], acc[mr][ntile][1]);
            *(__half2*)(Oh + r1o) = __floats2half2_rn(acc[mr][ntile][2], acc[mr][ntile][3]);
        }
    }
}

// ---------------------------------------------------------------------------
// 3) score: one warp per row. Main dot in fp32, 16 gathered negatives in fp16.
// ---------------------------------------------------------------------------
__global__ void score_kernel(const int* __restrict__ i1, const int* __restrict__ i2,
                             const int* __restrict__ i3, const int* __restrict__ i4,
                             const int* __restrict__ i5) {
    int warp = (blockIdx.x * blockDim.x + threadIdx.x) >> 5;
    int lane = threadIdx.x & 31;
    if (warp >= 61440) return;
    int R = warp;

    int kidx = 0;
#pragma unroll
    for (int k = 1; k < 5; k++)
        if (R >= d_rowbase[k]) kidx = k;
    int base = d_rowbase[kidx];
    int r = R - base;

    const int* idx;
    switch (kidx) {
        case 0: idx = i1; break;
        case 1: idx = i2; break;
        case 2: idx = i3; break;
        case 3: idx = i4; break;
        default: idx = i5; break;
    }

    int c0 = lane * 8;
    const float* ctx = g_ct + (size_t)r * 256 + c0;
    float4 cxa = *(const float4*)ctx;
    float4 cxb = *(const float4*)(ctx + 4);

    float l[17];
    // main dot in fp32
    {
        const float* tr = g_ztwk + (size_t)R * 256 + c0;
        float4 ta = *(const float4*)tr;
        float4 tb = *(const float4*)(tr + 4);
        l[0] = cxa.x * ta.x + cxa.y * ta.y + cxa.z * ta.z + cxa.w * ta.w +
               cxb.x * tb.x + cxb.y * tb.y + cxb.z * tb.z + cxb.w * tb.w;
    }
    // 16 negatives from fp16 copy
#pragma unroll
    for (int t = 1; t < 17; t++) {
        int row = base + idx[r * NNEG + (t - 1)];
        const __half* tr = g_ztwk_h + (size_t)row * 256 + c0;
        uint4 u = *(const uint4*)tr;     // 8 halves
        float2 f0 = __half22float2(*(const __half2*)&u.x);
        float2 f1 = __half22float2(*(const __half2*)&u.y);
        float2 f2 = __half22float2(*(const __half2*)&u.z);
        float2 f3 = __half22float2(*(const __half2*)&u.w);
        l[t] = cxa.x * f0.x + cxa.y * f0.y + cxa.z * f1.x + cxa.w * f1.y +
               cxb.x * f2.x + cxb.y * f2.y + cxb.z * f3.x + cxb.w * f3.y;
    }

#pragma unroll
    for (int o = 16; o >= 1; o >>= 1) {
#pragma unroll
        for (int t = 0; t < 17; t++) l[t] += __shfl_xor_sync(0xffffffffu, l[t], o);
    }

    if (lane == 0) {
        float m = l[0];
#pragma unroll
        for (int t = 1; t < 17; t++) m = fmaxf(m, l[t]);
        float S = 0.0f;
#pragma unroll
        for (int t = 0; t < 17; t++) S += __expf(l[t] - m);
        float p0 = __expf(l[0] - m) / S;
        g_loss[R] = -__logf(p0 + 1e-11f);
    }
}

// ---------------------------------------------------------------------------
// 4) patchwise loss + count
// ---------------------------------------------------------------------------
__global__ void patch_kernel(float* __restrict__ out) {
    int p = blockIdx.x * blockDim.x + threadIdx.x;  // b*256+h*16+w
    if (p >= 16384) return;
    int b = p >> 8;
    int h = (p >> 4) & 15;
    int w = p & 15;

    float s = 0.0f;
#pragma unroll
    for (int k = 0; k < 5; k++) {
        int off = k + 2;
        int Hk = 14 - k;
        int base = d_rowbase[k];
        if (h >= off) s += g_loss[base + (h - off) * 1024 + w * 64 + b];
        if (h < Hk)   s += g_loss[base + h * 1024 + w * 64 + b];
    }
    out[1 + p] = s;

    if (b == 0) {
        float cnt = 0.0f;
#pragma unroll
        for (int k = 0; k < 5; k++) {
            int off = k + 2;
            int Hk = 14 - k;
            cnt += (h >= off ? 1.0f : 0.0f) + (h < Hk ? 1.0f : 0.0f);
        }
        out[16385 + h * 16 + w] = cnt;
    }
}

// ---------------------------------------------------------------------------
// 5) total loss
// ---------------------------------------------------------------------------
__global__ void total_kernel(float* __restrict__ out) {
    __shared__ float red[256];
    const float scale[5] = {1.0f / (14336.0f * 5.0f), 1.0f / (13312.0f * 5.0f),
                            1.0f / (12288.0f * 5.0f), 1.0f / (11264.0f * 5.0f),
                            1.0f / (10240.0f * 5.0f)};
    int tid = threadIdx.x;
    float s = 0.0f;
    for (int R = tid; R < 61440; R += 256) {
        int kidx = 0;
#pragma unroll
        for (int k = 1; k < 5; k++)
            if (R >= d_rowbase[k]) kidx = k;
        s += g_loss[R] * scale[kidx];
    }
    red[tid] = s;
    __syncthreads();
    for (int o = 128; o > 0; o >>= 1) {
        if (tid < o) red[tid] += red[tid + o];
        __syncthreads();
    }
    if (tid == 0) out[0] = red[0];
}

// ---------------------------------------------------------------------------
extern "C" void kernel_launch(void* const* d_in, const int* in_sizes, int n_in,
                              void* d_out, int out_size) {
    const float* z  = (const float*)d_in[0];
    const float* c  = (const float*)d_in[1];
    const float* Wk = (const float*)d_in[2];
    const int* i1 = (const int*)d_in[3];
    const int* i2 = (const int*)d_in[4];
    const int* i3 = (const int*)d_in[5];
    const int* i4 = (const int*)d_in[6];
    const int* i5 = (const int*)d_in[7];
    float* out = (float*)d_out;

    cudaFuncSetAttribute(gemm_mma_kernel,
                         cudaFuncAttributeMaxDynamicSharedMemorySize, SM_TOTAL);

    split_kernel<<<3328, 256>>>(z, c, Wk);
    gemm_mma_kernel<<<960, 256, SM_TOTAL>>>();
    score_kernel<<<7680, 256>>>(i1, i2, i3, i4, i5);
    patch_kernel<<<64, 256>>>(out);
    total_kernel<<<1, 256>>>(out);
}